// round 4
// baseline (speedup 1.0000x reference)
#include <cuda_runtime.h>

#define BATCH 64
#define TLEN 512
#define HDIM 768
#define NLAB 9
#define START_ID 7
#define NEG_INF_F (-10000.0f)

// Scratch for features [B, T, L]
__device__ float g_feats[BATCH * TLEN * NLAB];

// ---------------------------------------------------------------------------
// Kernel A: feats = hidden_states @ W + b
// warp handles 4 consecutive rows (row = b*T + t); W transposed in shared.
// ---------------------------------------------------------------------------
__global__ void __launch_bounds__(256) feats_kernel(
    const float* __restrict__ hs,     // [B*T, H]
    const float* __restrict__ W,      // [H, L]
    const float* __restrict__ bias)   // [L]
{
    __shared__ float Wt[NLAB * HDIM];   // [l][h], row = 768 floats (16B aligned)

    int tid = threadIdx.x;
    for (int i = tid; i < HDIM * NLAB; i += blockDim.x) {
        int h = i / NLAB;
        int l = i - h * NLAB;
        Wt[l * HDIM + h] = W[i];
    }
    __syncthreads();

    int lane = tid & 31;
    int warp = tid >> 5;
    int row0 = (blockIdx.x * 8 + warp) * 4;   // 1024 blocks * 8 warps * 4 rows = 32768

    float acc[4][NLAB];
#pragma unroll
    for (int r = 0; r < 4; r++)
#pragma unroll
        for (int l = 0; l < NLAB; l++) acc[r][l] = 0.0f;

    const float4* WT4 = (const float4*)Wt;    // [l][192]

#pragma unroll
    for (int k = 0; k < 6; k++) {
        int j = k * 32 + lane;                // float4 index within row
        float4 x[4];
#pragma unroll
        for (int r = 0; r < 4; r++)
            x[r] = ((const float4*)(hs + (row0 + r) * HDIM))[j];
#pragma unroll
        for (int l = 0; l < NLAB; l++) {
            float4 w = WT4[l * 192 + j];
#pragma unroll
            for (int r = 0; r < 4; r++)
                acc[r][l] += x[r].x * w.x + x[r].y * w.y + x[r].z * w.z + x[r].w * w.w;
        }
    }

    // Cross-lane reduce: lane l ends holding full dot for label l (per row r)
    float res[4] = {0.f, 0.f, 0.f, 0.f};
#pragma unroll
    for (int l = 0; l < NLAB; l++) {
#pragma unroll
        for (int r = 0; r < 4; r++) {
            float v = acc[r][l];
            v += __shfl_xor_sync(0xffffffffu, v, 16);
            v += __shfl_xor_sync(0xffffffffu, v, 8);
            v += __shfl_xor_sync(0xffffffffu, v, 4);
            v += __shfl_xor_sync(0xffffffffu, v, 2);
            v += __shfl_xor_sync(0xffffffffu, v, 1);
            if (lane == l) res[r] = v;
        }
    }

    if (lane < NLAB) {
        float bb = bias[lane];
#pragma unroll
        for (int r = 0; r < 4; r++)
            g_feats[(row0 + r) * NLAB + lane] = res[r] + bb;
    }
}

// ---------------------------------------------------------------------------
// Kernel B: Viterbi forward + backtrack. One block (1 warp) per batch element.
// Lane l (< 9) owns label l. delta kept per-lane, gathered via shfl.
// psi (backpointers) live in shared memory. Output written as float32.
// ---------------------------------------------------------------------------
__global__ void __launch_bounds__(32) viterbi_kernel(
    const float* __restrict__ trans,  // [L, L], trans[to*L + from]
    float* __restrict__ out)          // [B, T] float32
{
    __shared__ unsigned char psi[(TLEN - 1) * NLAB];

    int b = blockIdx.x;
    int lane = threadIdx.x;
    int myl = lane < NLAB ? lane : 0;

    float tr[NLAB];
#pragma unroll
    for (int f = 0; f < NLAB; f++) tr[f] = trans[myl * NLAB + f];

    const float* fb = g_feats + b * TLEN * NLAB;

    float d = (lane == START_ID) ? 0.0f : NEG_INF_F;

    for (int t = 1; t < TLEN; t++) {
        float feat = fb[t * NLAB + myl];

        float s[NLAB], v[NLAB];
#pragma unroll
        for (int f = 0; f < NLAB; f++) s[f] = __shfl_sync(0xffffffffu, d, f);
#pragma unroll
        for (int f = 0; f < NLAB; f++) v[f] = tr[f] + s[f];

        // max via balanced tree (critical path)
        float m01 = fmaxf(v[0], v[1]);
        float m23 = fmaxf(v[2], v[3]);
        float m45 = fmaxf(v[4], v[5]);
        float m67 = fmaxf(v[6], v[7]);
        float m03 = fmaxf(m01, m23);
        float m47 = fmaxf(m45, m67);
        float m07 = fmaxf(m03, m47);
        float best = fmaxf(m07, v[8]);

        d = best + feat;   // next-iteration dependency — keep short

        // argmax (first max index) — off the critical path
        int bi = 8;
#pragma unroll
        for (int f = 7; f >= 0; f--)
            if (v[f] >= best) bi = f;   // descending scan -> min index among ties

        if (lane < NLAB) psi[(t - 1) * NLAB + lane] = (unsigned char)bi;
    }

    __syncwarp();

    // Gather final deltas; lane 0 does argmax + backtrack
    float fin[NLAB];
#pragma unroll
    for (int f = 0; f < NLAB; f++) fin[f] = __shfl_sync(0xffffffffu, d, f);

    if (lane == 0) {
        float best = fin[0];
        int p = 0;
#pragma unroll
        for (int f = 1; f < NLAB; f++)
            if (fin[f] > best) { best = fin[f]; p = f; }

        float* ob = out + b * TLEN;
        ob[TLEN - 1] = (float)p;
        for (int t = TLEN - 2; t >= 0; t--) {
            p = psi[t * NLAB + p];
            ob[t] = (float)p;
        }
    }
}

// ---------------------------------------------------------------------------
extern "C" void kernel_launch(void* const* d_in, const int* in_sizes, int n_in,
                              void* d_out, int out_size)
{
    // Bind inputs by element count (robust to metadata ordering):
    //   hidden_states: 64*512*768 = 25165824
    //   W:             768*9      = 6912
    //   b:             9
    //   transitions:   9*9        = 81
    const float* hidden = nullptr;
    const float* W      = nullptr;
    const float* bias   = nullptr;
    const float* trans  = nullptr;

    for (int i = 0; i < n_in; i++) {
        switch (in_sizes[i]) {
            case BATCH * TLEN * HDIM: hidden = (const float*)d_in[i]; break;
            case HDIM * NLAB:         W      = (const float*)d_in[i]; break;
            case NLAB:                bias   = (const float*)d_in[i]; break;
            case NLAB * NLAB:         trans  = (const float*)d_in[i]; break;
            default: break;
        }
    }

    float* out = (float*)d_out;   // [B, T] written as float32 label values

    feats_kernel<<<1024, 256>>>(hidden, W, bias);
    viterbi_kernel<<<BATCH, 32>>>(trans, out);
}

// round 5
// speedup vs baseline: 1.6308x; 1.6308x over previous
#include <cuda_runtime.h>

#define BATCH 64
#define TLEN 512
#define HDIM 768
#define NLAB 9
#define START_ID 7
#define NEG_INF_F (-10000.0f)

// Scratch for features [B, T, L]
__device__ float g_feats[BATCH * TLEN * NLAB];

// ---------------------------------------------------------------------------
// Kernel A: feats = hidden_states @ W + b
// warp handles 4 consecutive rows (row = b*T + t); W transposed in shared.
// ---------------------------------------------------------------------------
__global__ void __launch_bounds__(256) feats_kernel(
    const float* __restrict__ hs,     // [B*T, H]
    const float* __restrict__ W,      // [H, L]
    const float* __restrict__ bias)   // [L]
{
    __shared__ float Wt[NLAB * HDIM];   // [l][h]

    int tid = threadIdx.x;
    for (int i = tid; i < HDIM * NLAB; i += blockDim.x) {
        int h = i / NLAB;
        int l = i - h * NLAB;
        Wt[l * HDIM + h] = W[i];
    }
    __syncthreads();

    int lane = tid & 31;
    int warp = tid >> 5;
    int row0 = (blockIdx.x * 8 + warp) * 4;

    float acc[4][NLAB];
#pragma unroll
    for (int r = 0; r < 4; r++)
#pragma unroll
        for (int l = 0; l < NLAB; l++) acc[r][l] = 0.0f;

    const float4* WT4 = (const float4*)Wt;

#pragma unroll
    for (int k = 0; k < 6; k++) {
        int j = k * 32 + lane;
        float4 x[4];
#pragma unroll
        for (int r = 0; r < 4; r++)
            x[r] = ((const float4*)(hs + (row0 + r) * HDIM))[j];
#pragma unroll
        for (int l = 0; l < NLAB; l++) {
            float4 w = WT4[l * 192 + j];
#pragma unroll
            for (int r = 0; r < 4; r++)
                acc[r][l] += x[r].x * w.x + x[r].y * w.y + x[r].z * w.z + x[r].w * w.w;
        }
    }

    float res[4] = {0.f, 0.f, 0.f, 0.f};
#pragma unroll
    for (int l = 0; l < NLAB; l++) {
#pragma unroll
        for (int r = 0; r < 4; r++) {
            float v = acc[r][l];
            v += __shfl_xor_sync(0xffffffffu, v, 16);
            v += __shfl_xor_sync(0xffffffffu, v, 8);
            v += __shfl_xor_sync(0xffffffffu, v, 4);
            v += __shfl_xor_sync(0xffffffffu, v, 2);
            v += __shfl_xor_sync(0xffffffffu, v, 1);
            if (lane == l) res[r] = v;
        }
    }

    if (lane < NLAB) {
        float bb = bias[lane];
#pragma unroll
        for (int r = 0; r < 4; r++)
            g_feats[(row0 + r) * NLAB + lane] = res[r] + bb;
    }
}

// ---------------------------------------------------------------------------
// Kernel B: Viterbi forward + backtrack. One block (1 warp) per batch element.
// feats staged into SMEM up front (kills per-step L2 latency on the critical
// path). Lane l (< 9) owns label l; delta exchanged via shfl.
// ---------------------------------------------------------------------------
__global__ void __launch_bounds__(32) viterbi_kernel(
    const float* __restrict__ trans,  // [L, L], trans[to*L + from]
    float* __restrict__ out)          // [B, T] float32
{
    __shared__ float sfeats[TLEN * NLAB + NLAB];     // +1 row pad for prefetch
    __shared__ unsigned char psi[(TLEN - 1) * NLAB];

    int b = blockIdx.x;
    int lane = threadIdx.x;
    int myl = lane < NLAB ? lane : 0;

    // ---- Stage this batch's feats into SMEM (coalesced float4, high MLP) ----
    {
        const float4* src = (const float4*)(g_feats + b * TLEN * NLAB); // 1152 float4
        float4* dst = (float4*)sfeats;
#pragma unroll
        for (int i = 0; i < 36; i++)
            dst[i * 32 + lane] = src[i * 32 + lane];
    }

    float tr[NLAB];
#pragma unroll
    for (int f = 0; f < NLAB; f++) tr[f] = trans[myl * NLAB + f];

    __syncwarp();

    float d = (lane == START_ID) ? 0.0f : NEG_INF_F;
    float feat = sfeats[1 * NLAB + myl];

    for (int t = 1; t < TLEN; t++) {
        // prefetch next step's feat (pad row makes t+1==TLEN safe)
        float feat_next = sfeats[(t + 1) * NLAB + myl];

        float s[NLAB], v[NLAB];
#pragma unroll
        for (int f = 0; f < NLAB; f++) s[f] = __shfl_sync(0xffffffffu, d, f);
#pragma unroll
        for (int f = 0; f < NLAB; f++) v[f] = tr[f] + s[f];

        float m01 = fmaxf(v[0], v[1]);
        float m23 = fmaxf(v[2], v[3]);
        float m45 = fmaxf(v[4], v[5]);
        float m67 = fmaxf(v[6], v[7]);
        float m03 = fmaxf(m01, m23);
        float m47 = fmaxf(m45, m67);
        float m07 = fmaxf(m03, m47);
        float best = fmaxf(m07, v[8]);

        d = best + feat;   // critical-path update

        // argmax (first-index tie-break) — off the critical path
        int bi = 8;
#pragma unroll
        for (int f = 7; f >= 0; f--)
            if (v[f] >= best) bi = f;

        if (lane < NLAB) psi[(t - 1) * NLAB + lane] = (unsigned char)bi;

        feat = feat_next;
    }

    __syncwarp();

    float fin[NLAB];
#pragma unroll
    for (int f = 0; f < NLAB; f++) fin[f] = __shfl_sync(0xffffffffu, d, f);

    if (lane == 0) {
        float best = fin[0];
        int p = 0;
#pragma unroll
        for (int f = 1; f < NLAB; f++)
            if (fin[f] > best) { best = fin[f]; p = f; }

        float* ob = out + b * TLEN;
        ob[TLEN - 1] = (float)p;
        for (int t = TLEN - 2; t >= 0; t--) {
            p = psi[t * NLAB + p];
            ob[t] = (float)p;
        }
    }
}

// ---------------------------------------------------------------------------
extern "C" void kernel_launch(void* const* d_in, const int* in_sizes, int n_in,
                              void* d_out, int out_size)
{
    const float* hidden = nullptr;
    const float* W      = nullptr;
    const float* bias   = nullptr;
    const float* trans  = nullptr;

    for (int i = 0; i < n_in; i++) {
        switch (in_sizes[i]) {
            case BATCH * TLEN * HDIM: hidden = (const float*)d_in[i]; break;
            case HDIM * NLAB:         W      = (const float*)d_in[i]; break;
            case NLAB:                bias   = (const float*)d_in[i]; break;
            case NLAB * NLAB:         trans  = (const float*)d_in[i]; break;
            default: break;
        }
    }

    float* out = (float*)d_out;

    feats_kernel<<<1024, 256>>>(hidden, W, bias);
    viterbi_kernel<<<BATCH, 32>>>(trans, out);
}

// round 6
// speedup vs baseline: 1.9166x; 1.1752x over previous
#include <cuda_runtime.h>

#define BATCH 64
#define TLEN 512
#define HDIM 768
#define NLAB 9
#define START_ID 7
#define NEG_INF_F (-10000.0f)

// Scratch for features [B, T, L]
__device__ float g_feats[BATCH * TLEN * NLAB];

// ---------------------------------------------------------------------------
// Kernel A: feats = hidden_states @ W + b
// ---------------------------------------------------------------------------
__global__ void __launch_bounds__(256) feats_kernel(
    const float* __restrict__ hs,     // [B*T, H]
    const float* __restrict__ W,      // [H, L]
    const float* __restrict__ bias)   // [L]
{
    __shared__ float Wt[NLAB * HDIM];   // [l][h]

    int tid = threadIdx.x;
    for (int i = tid; i < HDIM * NLAB; i += blockDim.x) {
        int h = i / NLAB;
        int l = i - h * NLAB;
        Wt[l * HDIM + h] = W[i];
    }
    __syncthreads();

    int lane = tid & 31;
    int warp = tid >> 5;
    int row0 = (blockIdx.x * 8 + warp) * 4;

    float acc[4][NLAB];
#pragma unroll
    for (int r = 0; r < 4; r++)
#pragma unroll
        for (int l = 0; l < NLAB; l++) acc[r][l] = 0.0f;

    const float4* WT4 = (const float4*)Wt;

#pragma unroll
    for (int k = 0; k < 6; k++) {
        int j = k * 32 + lane;
        float4 x[4];
#pragma unroll
        for (int r = 0; r < 4; r++)
            x[r] = ((const float4*)(hs + (row0 + r) * HDIM))[j];
#pragma unroll
        for (int l = 0; l < NLAB; l++) {
            float4 w = WT4[l * 192 + j];
#pragma unroll
            for (int r = 0; r < 4; r++)
                acc[r][l] += x[r].x * w.x + x[r].y * w.y + x[r].z * w.z + x[r].w * w.w;
        }
    }

    float res[4] = {0.f, 0.f, 0.f, 0.f};
#pragma unroll
    for (int l = 0; l < NLAB; l++) {
#pragma unroll
        for (int r = 0; r < 4; r++) {
            float v = acc[r][l];
            v += __shfl_xor_sync(0xffffffffu, v, 16);
            v += __shfl_xor_sync(0xffffffffu, v, 8);
            v += __shfl_xor_sync(0xffffffffu, v, 4);
            v += __shfl_xor_sync(0xffffffffu, v, 2);
            v += __shfl_xor_sync(0xffffffffu, v, 1);
            if (lane == l) res[r] = v;
        }
    }

    if (lane < NLAB) {
        float bb = bias[lane];
#pragma unroll
        for (int r = 0; r < 4; r++)
            g_feats[(row0 + r) * NLAB + lane] = res[r] + bb;
    }
}

// ---------------------------------------------------------------------------
// Kernel B: Viterbi. One warp per batch element. feats staged in SMEM.
// argmax via balanced (value,index) tournament tree — no serial select chain.
// ---------------------------------------------------------------------------
__global__ void __launch_bounds__(32) viterbi_kernel(
    const float* __restrict__ trans,  // [L, L], trans[to*L + from]
    float* __restrict__ out)          // [B, T] float32
{
    __shared__ float sfeats[TLEN * NLAB + NLAB];     // +1 row pad for prefetch
    __shared__ unsigned char psi[(TLEN - 1) * NLAB];

    int b = blockIdx.x;
    int lane = threadIdx.x;
    int myl = lane < NLAB ? lane : 0;

    // Stage this batch's feats into SMEM (coalesced float4, high MLP)
    {
        const float4* src = (const float4*)(g_feats + b * TLEN * NLAB); // 1152 f4
        float4* dst = (float4*)sfeats;
#pragma unroll
        for (int i = 0; i < 36; i++)
            dst[i * 32 + lane] = src[i * 32 + lane];
    }

    float tr[NLAB];
#pragma unroll
    for (int f = 0; f < NLAB; f++) tr[f] = trans[myl * NLAB + f];

    __syncwarp();

    float d = (lane == START_ID) ? 0.0f : NEG_INF_F;
    float feat = sfeats[1 * NLAB + myl];

    for (int t = 1; t < TLEN; t++) {
        float feat_next = sfeats[(t + 1) * NLAB + myl];   // pad row covers t+1==TLEN

        float s[NLAB], v[NLAB];
#pragma unroll
        for (int f = 0; f < NLAB; f++) s[f] = __shfl_sync(0xffffffffu, d, f);
#pragma unroll
        for (int f = 0; f < NLAB; f++) v[f] = tr[f] + s[f];

        // (value,index) tournament tree, depth 4; left-priority '>=' keeps
        // the first (lowest) index among ties, matching jnp.argmax.
        float m01 = fmaxf(v[0], v[1]);  int i01 = (v[0] >= v[1]) ? 0 : 1;
        float m23 = fmaxf(v[2], v[3]);  int i23 = (v[2] >= v[3]) ? 2 : 3;
        float m45 = fmaxf(v[4], v[5]);  int i45 = (v[4] >= v[5]) ? 4 : 5;
        float m67 = fmaxf(v[6], v[7]);  int i67 = (v[6] >= v[7]) ? 6 : 7;
        float m03 = fmaxf(m01, m23);    int i03 = (m01 >= m23) ? i01 : i23;
        float m47 = fmaxf(m45, m67);    int i47 = (m45 >= m67) ? i45 : i67;
        float m07 = fmaxf(m03, m47);    int i07 = (m03 >= m47) ? i03 : i47;
        float best = fmaxf(m07, v[8]);

        d = best + feat;                 // critical-path update (short)

        int bi = (m07 >= v[8]) ? i07 : 8;
        if (lane < NLAB) psi[(t - 1) * NLAB + lane] = (unsigned char)bi;

        feat = feat_next;
    }

    __syncwarp();

    float fin[NLAB];
#pragma unroll
    for (int f = 0; f < NLAB; f++) fin[f] = __shfl_sync(0xffffffffu, d, f);

    if (lane == 0) {
        // argmax over final deltas (first-index tie-break)
        float best = fin[0];
        int p = 0;
#pragma unroll
        for (int f = 1; f < NLAB; f++)
            if (fin[f] > best) { best = fin[f]; p = f; }

        float* ob = out + b * TLEN;
        ob[TLEN - 1] = (float)p;
        for (int t = TLEN - 2; t >= 0; t--) {
            p = psi[t * NLAB + p];
            ob[t] = (float)p;
        }
    }
}

// ---------------------------------------------------------------------------
extern "C" void kernel_launch(void* const* d_in, const int* in_sizes, int n_in,
                              void* d_out, int out_size)
{
    const float* hidden = nullptr;
    const float* W      = nullptr;
    const float* bias   = nullptr;
    const float* trans  = nullptr;

    for (int i = 0; i < n_in; i++) {
        switch (in_sizes[i]) {
            case BATCH * TLEN * HDIM: hidden = (const float*)d_in[i]; break;
            case HDIM * NLAB:         W      = (const float*)d_in[i]; break;
            case NLAB:                bias   = (const float*)d_in[i]; break;
            case NLAB * NLAB:         trans  = (const float*)d_in[i]; break;
            default: break;
        }
    }

    float* out = (float*)d_out;

    feats_kernel<<<1024, 256>>>(hidden, W, bias);
    viterbi_kernel<<<BATCH, 32>>>(trans, out);
}

// round 7
// speedup vs baseline: 2.1290x; 1.1109x over previous
#include <cuda_runtime.h>

#define BATCH 64
#define TLEN 512
#define HDIM 768
#define NLAB 9
#define START_ID 7
#define NEG_INF_F (-10000.0f)

// Scratch for features [B, T, L]
__device__ float g_feats[BATCH * TLEN * NLAB];

// ---------------------------------------------------------------------------
// Kernel A: feats = hidden_states @ W + b
// Warp handles 4 rows; k split over 32 lanes; reduction via SMEM transpose
// (reusing the Wt buffer) instead of 180 warp shuffles.
// ---------------------------------------------------------------------------
__global__ void __launch_bounds__(256) feats_kernel(
    const float* __restrict__ hs,     // [B*T, H]
    const float* __restrict__ W,      // [H, L]
    const float* __restrict__ bias)   // [L]
{
    __shared__ float Wt[NLAB * HDIM];   // 27648 B; reused as reduction scratch

    int tid = threadIdx.x;
    for (int i = tid; i < HDIM * NLAB; i += blockDim.x) {
        int h = i / NLAB;
        int l = i - h * NLAB;
        Wt[l * HDIM + h] = W[i];
    }
    __syncthreads();

    int lane = tid & 31;
    int warp = tid >> 5;
    int row0 = (blockIdx.x * 8 + warp) * 4;

    float acc[4][NLAB];
#pragma unroll
    for (int r = 0; r < 4; r++)
#pragma unroll
        for (int l = 0; l < NLAB; l++) acc[r][l] = 0.0f;

    const float4* WT4 = (const float4*)Wt;

#pragma unroll
    for (int k = 0; k < 6; k++) {
        int j = k * 32 + lane;
        float4 x[4];
#pragma unroll
        for (int r = 0; r < 4; r++)
            x[r] = ((const float4*)(hs + (row0 + r) * HDIM))[j];
#pragma unroll
        for (int l = 0; l < NLAB; l++) {
            float4 w = WT4[l * 192 + j];
#pragma unroll
            for (int r = 0; r < 4; r++)
                acc[r][l] += x[r].x * w.x + x[r].y * w.y + x[r].z * w.z + x[r].w * w.w;
        }
    }

    // ---- Reduction via SMEM transpose (reuse Wt after barrier) ----
    __syncthreads();                       // all warps done reading Wt
    float* red = Wt + warp * 648;          // 18 pairs * 36-float stride

#pragma unroll
    for (int half = 0; half < 2; half++) {
#pragma unroll
        for (int p = 0; p < 18; p++) {
            int r = half * 2 + (p >= 9 ? 1 : 0);
            int l = (p >= 9) ? p - 9 : p;
            red[p * 36 + lane] = acc[r][l];
        }
        __syncwarp();
        if (lane < 18) {
            const float4* q = (const float4*)(red + lane * 36);
            float4 a = q[0], b2 = q[1], c2 = q[2], d2 = q[3];
            float4 e2 = q[4], f2 = q[5], g2 = q[6], h2 = q[7];
            float s0 = (a.x + a.y) + (a.z + a.w);
            float s1 = (b2.x + b2.y) + (b2.z + b2.w);
            float s2 = (c2.x + c2.y) + (c2.z + c2.w);
            float s3 = (d2.x + d2.y) + (d2.z + d2.w);
            float s4 = (e2.x + e2.y) + (e2.z + e2.w);
            float s5 = (f2.x + f2.y) + (f2.z + f2.w);
            float s6 = (g2.x + g2.y) + (g2.z + g2.w);
            float s7 = (h2.x + h2.y) + (h2.z + h2.w);
            float sum = ((s0 + s1) + (s2 + s3)) + ((s4 + s5) + (s6 + s7));
            int r = half * 2 + (lane >= 9 ? 1 : 0);
            int l = (lane >= 9) ? lane - 9 : lane;
            g_feats[(row0 + r) * NLAB + l] = sum + bias[l];
        }
        __syncwarp();
    }
}

// ---------------------------------------------------------------------------
// Kernel B: Viterbi. One warp per batch. Forward: lane=to, 8 live from-states
// (from=8 provably never argmax: trans[:,STOP]=-1e4). Backtrack: chunked
// 144-task parallel pointer-chase (integer-exact).
// ---------------------------------------------------------------------------
__global__ void __launch_bounds__(32) viterbi_kernel(
    const float* __restrict__ trans,  // [L, L], trans[to*L + from]
    float* __restrict__ out)          // [B, T] float32
{
    __shared__ float sfeats[TLEN * NLAB + NLAB];       // +pad row
    __shared__ unsigned char psi[(TLEN - 1) * NLAB];   // rows t=0..510: s_t = psi[t][s_{t+1}]
    __shared__ unsigned char path[16 * NLAB * 32];     // [chunk][exit][offset]

    int b = blockIdx.x;
    int lane = threadIdx.x;
    int myl = lane < NLAB ? lane : 0;

    // Stage feats for this batch (coalesced float4)
    {
        const float4* src = (const float4*)(g_feats + b * TLEN * NLAB);
        float4* dst = (float4*)sfeats;
#pragma unroll
        for (int i = 0; i < 36; i++)
            dst[i * 32 + lane] = src[i * 32 + lane];
    }

    float tr[8];
#pragma unroll
    for (int f = 0; f < 8; f++) tr[f] = trans[myl * NLAB + f];

    __syncwarp();

    float d = (lane == START_ID) ? 0.0f : NEG_INF_F;
    float feat = sfeats[1 * NLAB + myl];

    for (int t = 1; t < TLEN; t++) {
        float feat_next = sfeats[(t + 1) * NLAB + myl];

        float s[8], v[8];
#pragma unroll
        for (int f = 0; f < 8; f++) s[f] = __shfl_sync(0xffffffffu, d, f);
#pragma unroll
        for (int f = 0; f < 8; f++) v[f] = tr[f] + s[f];

        // (value,index) tournament over 8, left-priority '>=' (first-index ties)
        float m01 = fmaxf(v[0], v[1]);  int i01 = (v[0] >= v[1]) ? 0 : 1;
        float m23 = fmaxf(v[2], v[3]);  int i23 = (v[2] >= v[3]) ? 2 : 3;
        float m45 = fmaxf(v[4], v[5]);  int i45 = (v[4] >= v[5]) ? 4 : 5;
        float m67 = fmaxf(v[6], v[7]);  int i67 = (v[6] >= v[7]) ? 6 : 7;
        float m03 = fmaxf(m01, m23);    int i03 = (m01 >= m23) ? i01 : i23;
        float m47 = fmaxf(m45, m67);    int i47 = (m45 >= m67) ? i45 : i67;
        float m07 = fmaxf(m03, m47);

        d = m07 + feat;                 // short critical path

        int bi = (m03 >= m47) ? i03 : i47;
        if (lane < NLAB) psi[(t - 1) * NLAB + lane] = (unsigned char)bi;

        feat = feat_next;
    }

    __syncwarp();   // psi visible warp-wide

    // Final argmax (replicated in all lanes; full 9 states, first-index ties)
    float fin[NLAB];
#pragma unroll
    for (int f = 0; f < NLAB; f++) fin[f] = __shfl_sync(0xffffffffu, d, f);
    float best = fin[0];
    int last = 0;
#pragma unroll
    for (int f = 1; f < NLAB; f++)
        if (fin[f] > best) { best = fin[f]; last = f; }

    // ---- Phase B1: 144 backtrack tasks (16 chunks x 9 exits) ----
#pragma unroll
    for (int round = 0; round < 5; round++) {
        int task = round * 32 + lane;
        if (task < 16 * NLAB) {
            int c = task / NLAB;
            int x = task - c * NLAB;
            int lo = c * 32;
            int hi = (c == 15) ? 510 : lo + 31;
            int p = x;
            unsigned char* pc = &path[(c * NLAB + x) * 32];
            for (int t = hi; t >= lo; t--) {
                p = psi[t * NLAB + p];
                pc[t - lo] = (unsigned char)p;
            }
        }
    }
    __syncwarp();

    // ---- Phase B2: compose chunk exit states (replicated, 15-deep chain) ----
    int X[16];
    X[15] = last;
#pragma unroll
    for (int c = 15; c > 0; c--)
        X[c - 1] = path[(c * NLAB + X[c]) * 32];   // entry of chunk c = exit of c-1

    // ---- Phase B3: parallel output fill ----
    float* ob = out + b * TLEN;
#pragma unroll
    for (int i = 0; i < 16; i++) {
        int t = i * 32 + lane;
        int lbl = path[(i * NLAB + X[i]) * 32 + lane];
        if (t == TLEN - 1) lbl = last;             // offset 31 of chunk 15 unused
        ob[t] = (float)lbl;
    }
}

// ---------------------------------------------------------------------------
extern "C" void kernel_launch(void* const* d_in, const int* in_sizes, int n_in,
                              void* d_out, int out_size)
{
    const float* hidden = nullptr;
    const float* W      = nullptr;
    const float* bias   = nullptr;
    const float* trans  = nullptr;

    for (int i = 0; i < n_in; i++) {
        switch (in_sizes[i]) {
            case BATCH * TLEN * HDIM: hidden = (const float*)d_in[i]; break;
            case HDIM * NLAB:         W      = (const float*)d_in[i]; break;
            case NLAB:                bias   = (const float*)d_in[i]; break;
            case NLAB * NLAB:         trans  = (const float*)d_in[i]; break;
            default: break;
        }
    }

    float* out = (float*)d_out;

    feats_kernel<<<1024, 256>>>(hidden, W, bias);
    viterbi_kernel<<<BATCH, 32>>>(trans, out);
}

// round 9
// speedup vs baseline: 2.1433x; 1.0067x over previous
#include <cuda_runtime.h>

#define BATCH 64
#define TLEN 512
#define HDIM 768
#define NLAB 9
#define START_ID 7
#define NEG_INF_F (-10000.0f)

// Per-batch feats plane padded to a 16-byte multiple so plane 1 stays
// float4-aligned (4608 data + 9 pad -> 4620 floats = 18480 B).
#define SF_PLANE 4620

// Scratch for features [B, T, L]
__device__ float g_feats[BATCH * TLEN * NLAB];

// ---------------------------------------------------------------------------
// Kernel A: feats = hidden_states @ W + b
// 4 rows per warp; W transposed in SMEM; launch_bounds forces >=3 blocks/SM.
// ---------------------------------------------------------------------------
__global__ void __launch_bounds__(256, 3) feats_kernel(
    const float* __restrict__ hs,     // [B*T, H]
    const float* __restrict__ W,      // [H, L]
    const float* __restrict__ bias)   // [L]
{
    __shared__ float Wt[NLAB * HDIM];   // 27648 B; also reduction scratch

    int tid = threadIdx.x;
    for (int i = tid; i < HDIM * NLAB; i += blockDim.x) {
        int h = i / NLAB;
        int l = i - h * NLAB;
        Wt[l * HDIM + h] = W[i];
    }
    __syncthreads();

    int lane = tid & 31;
    int warp = tid >> 5;
    int row0 = (blockIdx.x * 8 + warp) * 4;

    float acc[4][NLAB];
#pragma unroll
    for (int r = 0; r < 4; r++)
#pragma unroll
        for (int l = 0; l < NLAB; l++) acc[r][l] = 0.0f;

    const float4* WT4 = (const float4*)Wt;

#pragma unroll
    for (int k = 0; k < 6; k++) {
        int j = k * 32 + lane;
        float4 x[4];
#pragma unroll
        for (int r = 0; r < 4; r++)
            x[r] = ((const float4*)(hs + (row0 + r) * HDIM))[j];
#pragma unroll
        for (int l = 0; l < NLAB; l++) {
            float4 w = WT4[l * 192 + j];
#pragma unroll
            for (int r = 0; r < 4; r++)
                acc[r][l] += x[r].x * w.x + x[r].y * w.y + x[r].z * w.z + x[r].w * w.w;
        }
    }

    // Reduction via SMEM transpose (reuse Wt after barrier)
    __syncthreads();
    float* red = Wt + warp * 648;

#pragma unroll
    for (int half = 0; half < 2; half++) {
#pragma unroll
        for (int p = 0; p < 18; p++) {
            int r = half * 2 + (p >= 9 ? 1 : 0);
            int l = (p >= 9) ? p - 9 : p;
            red[p * 36 + lane] = acc[r][l];
        }
        __syncwarp();
        if (lane < 18) {
            const float4* q = (const float4*)(red + lane * 36);
            float4 a = q[0], b2 = q[1], c2 = q[2], d2 = q[3];
            float4 e2 = q[4], f2 = q[5], g2 = q[6], h2 = q[7];
            float s0 = (a.x + a.y) + (a.z + a.w);
            float s1 = (b2.x + b2.y) + (b2.z + b2.w);
            float s2 = (c2.x + c2.y) + (c2.z + c2.w);
            float s3 = (d2.x + d2.y) + (d2.z + d2.w);
            float s4 = (e2.x + e2.y) + (e2.z + e2.w);
            float s5 = (f2.x + f2.y) + (f2.z + f2.w);
            float s6 = (g2.x + g2.y) + (g2.z + g2.w);
            float s7 = (h2.x + h2.y) + (h2.z + h2.w);
            float sum = ((s0 + s1) + (s2 + s3)) + ((s4 + s5) + (s6 + s7));
            int r = half * 2 + (lane >= 9 ? 1 : 0);
            int l = (lane >= 9) ? lane - 9 : lane;
            g_feats[(row0 + r) * NLAB + l] = sum + bias[l];
        }
        __syncwarp();
    }
}

// ---------------------------------------------------------------------------
// Kernel B: Viterbi, TWO batches per warp (lanes 0-15 batch A, 16-31 batch B).
// ---------------------------------------------------------------------------
__global__ void __launch_bounds__(32) viterbi_kernel(
    const float* __restrict__ trans,  // [L, L], trans[to*L + from]
    float* __restrict__ out)          // [B, T] float32
{
    __shared__ float sfeats[2][SF_PLANE];                // 36.96 KB, planes 16B-aligned
    __shared__ unsigned char psi[2][(TLEN - 1) * NLAB];  // 9.2 KB

    // path overlays sfeats (sfeats dead after forward pass); 2 * 4608 bytes
    unsigned char* pathbuf = (unsigned char*)&sfeats[0][0];

    int lane = threadIdx.x;
    int half = lane >> 4;          // which batch within the warp
    int hl = lane & 15;
    int b = blockIdx.x * 2 + half;
    int myl = (hl < NLAB) ? hl : 0;
    int sbase = half << 4;

    // Stage feats for both batches (full warp on each, coalesced float4)
#pragma unroll
    for (int h2 = 0; h2 < 2; h2++) {
        const float4* src = (const float4*)(g_feats + (blockIdx.x * 2 + h2) * TLEN * NLAB);
        float4* dst = (float4*)sfeats[h2];
#pragma unroll
        for (int i = 0; i < 36; i++)
            dst[i * 32 + lane] = src[i * 32 + lane];
    }

    float tr[8];
#pragma unroll
    for (int f = 0; f < 8; f++) tr[f] = trans[myl * NLAB + f];

    __syncwarp();

    float d = (hl == START_ID) ? 0.0f : NEG_INF_F;
    float feat = sfeats[half][NLAB + myl];

    for (int t = 1; t < TLEN; t++) {
        float feat_next = sfeats[half][(t + 1) * NLAB + myl];  // pad covers t+1==TLEN

        float s[8], v[8];
#pragma unroll
        for (int f = 0; f < 8; f++) s[f] = __shfl_sync(0xffffffffu, d, sbase + f);
#pragma unroll
        for (int f = 0; f < 8; f++) v[f] = tr[f] + s[f];

        float m01 = fmaxf(v[0], v[1]);  int i01 = (v[0] >= v[1]) ? 0 : 1;
        float m23 = fmaxf(v[2], v[3]);  int i23 = (v[2] >= v[3]) ? 2 : 3;
        float m45 = fmaxf(v[4], v[5]);  int i45 = (v[4] >= v[5]) ? 4 : 5;
        float m67 = fmaxf(v[6], v[7]);  int i67 = (v[6] >= v[7]) ? 6 : 7;
        float m03 = fmaxf(m01, m23);    int i03 = (m01 >= m23) ? i01 : i23;
        float m47 = fmaxf(m45, m67);    int i47 = (m45 >= m67) ? i45 : i67;
        float m07 = fmaxf(m03, m47);

        d = m07 + feat;

        int bi = (m03 >= m47) ? i03 : i47;
        if (hl < NLAB) psi[half][(t - 1) * NLAB + hl] = (unsigned char)bi;

        feat = feat_next;
    }

    __syncwarp();   // psi complete; sfeats now dead -> safe to overlay path

    // Final argmax over 9 states (replicated per half, first-index ties)
    float fin[NLAB];
#pragma unroll
    for (int f = 0; f < NLAB; f++) fin[f] = __shfl_sync(0xffffffffu, d, sbase + f);
    float best = fin[0];
    int last = 0;
#pragma unroll
    for (int f = 1; f < NLAB; f++)
        if (fin[f] > best) { best = fin[f]; last = f; }

    unsigned char* mypath = pathbuf + half * (16 * NLAB * 32);
    const unsigned char* mypsi = psi[half];

    // Phase B1: 144 backtrack tasks per batch over 16 lanes -> 9 rounds
#pragma unroll
    for (int round = 0; round < 9; round++) {
        int task = round * 16 + hl;
        if (task < 16 * NLAB) {
            int c = task / NLAB;
            int x = task - c * NLAB;
            int lo = c * 32;
            int hi = (c == 15) ? 510 : lo + 31;
            int p = x;
            unsigned char* pc = mypath + (c * NLAB + x) * 32;
            for (int t = hi; t >= lo; t--) {
                p = mypsi[t * NLAB + p];
                pc[t - lo] = (unsigned char)p;
            }
        }
    }
    __syncwarp();

    // Phase B2: compose chunk exit states (replicated, 15-deep chain)
    int X[16];
    X[15] = last;
#pragma unroll
    for (int c = 15; c > 0; c--)
        X[c - 1] = mypath[(c * NLAB + X[c]) * 32];

    // Phase B3: parallel output fill (16 lanes per batch, 2 sub-steps/chunk)
    float* ob = out + b * TLEN;
#pragma unroll
    for (int c = 0; c < 16; c++) {
#pragma unroll
        for (int sub = 0; sub < 2; sub++) {
            int off = sub * 16 + hl;
            int t = c * 32 + off;
            int lbl = mypath[(c * NLAB + X[c]) * 32 + off];
            if (t == TLEN - 1) lbl = last;
            ob[t] = (float)lbl;
        }
    }
}

// ---------------------------------------------------------------------------
extern "C" void kernel_launch(void* const* d_in, const int* in_sizes, int n_in,
                              void* d_out, int out_size)
{
    const float* hidden = nullptr;
    const float* W      = nullptr;
    const float* bias   = nullptr;
    const float* trans  = nullptr;

    for (int i = 0; i < n_in; i++) {
        switch (in_sizes[i]) {
            case BATCH * TLEN * HDIM: hidden = (const float*)d_in[i]; break;
            case HDIM * NLAB:         W      = (const float*)d_in[i]; break;
            case NLAB:                bias   = (const float*)d_in[i]; break;
            case NLAB * NLAB:         trans  = (const float*)d_in[i]; break;
            default: break;
        }
    }

    float* out = (float*)d_out;

    feats_kernel<<<1024, 256>>>(hidden, W, bias);
    viterbi_kernel<<<BATCH / 2, 32>>>(trans, out);
}

// round 10
// speedup vs baseline: 2.2063x; 1.0294x over previous
#include <cuda_runtime.h>
#include <cstdint>

#define BATCH 64
#define TLEN 512
#define HDIM 768
#define NLAB 9
#define START_ID 7
#define NEG_INF_F (-10000.0f)

// Scratch for features [B, T, L]
__device__ float g_feats[BATCH * TLEN * NLAB];

#define PACK_F32X2(out, lo, hi) \
    asm("mov.b64 %0, {%1, %2};" : "=l"(out) : "f"(lo), "f"(hi))
#define UNPACK_F32X2(lo, hi, in) \
    asm("mov.b64 {%0, %1}, %2;" : "=f"(lo), "=f"(hi) : "l"(in))
#define FMA_F32X2(d, a, b, c) \
    asm("fma.rn.f32x2 %0, %1, %2, %3;" : "=l"(d) : "l"(a), "l"(b), "l"(c))

// ---------------------------------------------------------------------------
// Kernel A: feats = hidden_states @ W + b
// 4 rows per warp as 2 row-pairs in packed f32x2; FFMA2 halves FMA-pipe time.
// Per-component rounding identical to scalar FFMA (same order) -> exact.
// ---------------------------------------------------------------------------
__global__ void __launch_bounds__(256, 3) feats_kernel(
    const float* __restrict__ hs,     // [B*T, H]
    const float* __restrict__ W,      // [H, L]
    const float* __restrict__ bias)   // [L]
{
    __shared__ float Wt[NLAB * HDIM];   // 27648 B; also reduction scratch

    int tid = threadIdx.x;
    for (int i = tid; i < HDIM * NLAB; i += blockDim.x) {
        int h = i / NLAB;
        int l = i - h * NLAB;
        Wt[l * HDIM + h] = W[i];
    }
    __syncthreads();

    int lane = tid & 31;
    int warp = tid >> 5;
    int row0 = (blockIdx.x * 8 + warp) * 4;

    // acc2[p][l]: packed accumulators for row-pair p = (2p, 2p+1)
    unsigned long long acc2[2][NLAB];
#pragma unroll
    for (int p = 0; p < 2; p++)
#pragma unroll
        for (int l = 0; l < NLAB; l++) {
            float z = 0.0f;
            PACK_F32X2(acc2[p][l], z, z);
        }

    const float4* WT4 = (const float4*)Wt;

#pragma unroll
    for (int k = 0; k < 6; k++) {
        int j = k * 32 + lane;
        float4 x[4];
#pragma unroll
        for (int r = 0; r < 4; r++)
            x[r] = ((const float4*)(hs + (row0 + r) * HDIM))[j];

        // pack x: a2[p][comp] = (x[2p].comp, x[2p+1].comp)
        unsigned long long a2[2][4];
#pragma unroll
        for (int p = 0; p < 2; p++) {
            PACK_F32X2(a2[p][0], x[2 * p].x, x[2 * p + 1].x);
            PACK_F32X2(a2[p][1], x[2 * p].y, x[2 * p + 1].y);
            PACK_F32X2(a2[p][2], x[2 * p].z, x[2 * p + 1].z);
            PACK_F32X2(a2[p][3], x[2 * p].w, x[2 * p + 1].w);
        }

#pragma unroll
        for (int l = 0; l < NLAB; l++) {
            float4 w = WT4[l * 192 + j];
            unsigned long long w2[4];
            PACK_F32X2(w2[0], w.x, w.x);
            PACK_F32X2(w2[1], w.y, w.y);
            PACK_F32X2(w2[2], w.z, w.z);
            PACK_F32X2(w2[3], w.w, w.w);
#pragma unroll
            for (int p = 0; p < 2; p++) {
                FMA_F32X2(acc2[p][l], a2[p][0], w2[0], acc2[p][l]);
                FMA_F32X2(acc2[p][l], a2[p][1], w2[1], acc2[p][l]);
                FMA_F32X2(acc2[p][l], a2[p][2], w2[2], acc2[p][l]);
                FMA_F32X2(acc2[p][l], a2[p][3], w2[3], acc2[p][l]);
            }
        }
    }

    // Unpack to per-row accumulators
    float acc[4][NLAB];
#pragma unroll
    for (int p = 0; p < 2; p++)
#pragma unroll
        for (int l = 0; l < NLAB; l++)
            UNPACK_F32X2(acc[2 * p][l], acc[2 * p + 1][l], acc2[p][l]);

    // Reduction via SMEM transpose (reuse Wt after barrier)
    __syncthreads();
    float* red = Wt + warp * 648;

#pragma unroll
    for (int half = 0; half < 2; half++) {
#pragma unroll
        for (int p = 0; p < 18; p++) {
            int r = half * 2 + (p >= 9 ? 1 : 0);
            int l = (p >= 9) ? p - 9 : p;
            red[p * 36 + lane] = acc[r][l];
        }
        __syncwarp();
        if (lane < 18) {
            const float4* q = (const float4*)(red + lane * 36);
            float4 a = q[0], b2 = q[1], c2 = q[2], d2 = q[3];
            float4 e2 = q[4], f2 = q[5], g2 = q[6], h2 = q[7];
            float s0 = (a.x + a.y) + (a.z + a.w);
            float s1 = (b2.x + b2.y) + (b2.z + b2.w);
            float s2 = (c2.x + c2.y) + (c2.z + c2.w);
            float s3 = (d2.x + d2.y) + (d2.z + d2.w);
            float s4 = (e2.x + e2.y) + (e2.z + e2.w);
            float s5 = (f2.x + f2.y) + (f2.z + f2.w);
            float s6 = (g2.x + g2.y) + (g2.z + g2.w);
            float s7 = (h2.x + h2.y) + (h2.z + h2.w);
            float sum = ((s0 + s1) + (s2 + s3)) + ((s4 + s5) + (s6 + s7));
            int r = half * 2 + (lane >= 9 ? 1 : 0);
            int l = (lane >= 9) ? lane - 9 : lane;
            g_feats[(row0 + r) * NLAB + l] = sum + bias[l];
        }
        __syncwarp();
    }
}

// ---------------------------------------------------------------------------
// Kernel B: Viterbi (Round-7 proven version). One warp per batch element.
// ---------------------------------------------------------------------------
__global__ void __launch_bounds__(32) viterbi_kernel(
    const float* __restrict__ trans,  // [L, L], trans[to*L + from]
    float* __restrict__ out)          // [B, T] float32
{
    __shared__ float sfeats[TLEN * NLAB + NLAB];       // +pad row
    __shared__ unsigned char psi[(TLEN - 1) * NLAB];
    __shared__ unsigned char path[16 * NLAB * 32];

    int b = blockIdx.x;
    int lane = threadIdx.x;
    int myl = lane < NLAB ? lane : 0;

    {
        const float4* src = (const float4*)(g_feats + b * TLEN * NLAB);
        float4* dst = (float4*)sfeats;
#pragma unroll
        for (int i = 0; i < 36; i++)
            dst[i * 32 + lane] = src[i * 32 + lane];
    }

    float tr[8];
#pragma unroll
    for (int f = 0; f < 8; f++) tr[f] = trans[myl * NLAB + f];

    __syncwarp();

    float d = (lane == START_ID) ? 0.0f : NEG_INF_F;
    float feat = sfeats[1 * NLAB + myl];

    for (int t = 1; t < TLEN; t++) {
        float feat_next = sfeats[(t + 1) * NLAB + myl];

        float s[8], v[8];
#pragma unroll
        for (int f = 0; f < 8; f++) s[f] = __shfl_sync(0xffffffffu, d, f);
#pragma unroll
        for (int f = 0; f < 8; f++) v[f] = tr[f] + s[f];

        float m01 = fmaxf(v[0], v[1]);  int i01 = (v[0] >= v[1]) ? 0 : 1;
        float m23 = fmaxf(v[2], v[3]);  int i23 = (v[2] >= v[3]) ? 2 : 3;
        float m45 = fmaxf(v[4], v[5]);  int i45 = (v[4] >= v[5]) ? 4 : 5;
        float m67 = fmaxf(v[6], v[7]);  int i67 = (v[6] >= v[7]) ? 6 : 7;
        float m03 = fmaxf(m01, m23);    int i03 = (m01 >= m23) ? i01 : i23;
        float m47 = fmaxf(m45, m67);    int i47 = (m45 >= m67) ? i45 : i67;
        float m07 = fmaxf(m03, m47);

        d = m07 + feat;

        int bi = (m03 >= m47) ? i03 : i47;
        if (lane < NLAB) psi[(t - 1) * NLAB + lane] = (unsigned char)bi;

        feat = feat_next;
    }

    __syncwarp();

    float fin[NLAB];
#pragma unroll
    for (int f = 0; f < NLAB; f++) fin[f] = __shfl_sync(0xffffffffu, d, f);
    float best = fin[0];
    int last = 0;
#pragma unroll
    for (int f = 1; f < NLAB; f++)
        if (fin[f] > best) { best = fin[f]; last = f; }

    // Phase B1: 144 backtrack tasks (16 chunks x 9 exits)
#pragma unroll
    for (int round = 0; round < 5; round++) {
        int task = round * 32 + lane;
        if (task < 16 * NLAB) {
            int c = task / NLAB;
            int x = task - c * NLAB;
            int lo = c * 32;
            int hi = (c == 15) ? 510 : lo + 31;
            int p = x;
            unsigned char* pc = &path[(c * NLAB + x) * 32];
            for (int t = hi; t >= lo; t--) {
                p = psi[t * NLAB + p];
                pc[t - lo] = (unsigned char)p;
            }
        }
    }
    __syncwarp();

    // Phase B2: compose chunk exit states
    int X[16];
    X[15] = last;
#pragma unroll
    for (int c = 15; c > 0; c--)
        X[c - 1] = path[(c * NLAB + X[c]) * 32];

    // Phase B3: parallel output fill
    float* ob = out + b * TLEN;
#pragma unroll
    for (int i = 0; i < 16; i++) {
        int t = i * 32 + lane;
        int lbl = path[(i * NLAB + X[i]) * 32 + lane];
        if (t == TLEN - 1) lbl = last;
        ob[t] = (float)lbl;
    }
}

// ---------------------------------------------------------------------------
extern "C" void kernel_launch(void* const* d_in, const int* in_sizes, int n_in,
                              void* d_out, int out_size)
{
    const float* hidden = nullptr;
    const float* W      = nullptr;
    const float* bias   = nullptr;
    const float* trans  = nullptr;

    for (int i = 0; i < n_in; i++) {
        switch (in_sizes[i]) {
            case BATCH * TLEN * HDIM: hidden = (const float*)d_in[i]; break;
            case HDIM * NLAB:         W      = (const float*)d_in[i]; break;
            case NLAB:                bias   = (const float*)d_in[i]; break;
            case NLAB * NLAB:         trans  = (const float*)d_in[i]; break;
            default: break;
        }
    }

    float* out = (float*)d_out;

    feats_kernel<<<1024, 256>>>(hidden, W, bias);
    viterbi_kernel<<<BATCH, 32>>>(trans, out);
}